// round 1
// baseline (speedup 1.0000x reference)
#include <cuda_runtime.h>
#include <cuda_bf16.h>
#include <cstdint>

#define MAXN 40000
#define MAXG 64
#define HDIM 128

__device__ float g_h[MAXN * HDIM];
__device__ float g_agg[MAXN * HDIM];
__device__ float g_dinv[MAXN];
__device__ int   g_deg[MAXN];
__device__ float g_pool_add[MAXG * HDIM];
__device__ int   g_pool_max[MAXG * HDIM];
__device__ int   g_count[MAXG];

__device__ __forceinline__ int enc_f(float f) {
    int i = __float_as_int(f);
    return i >= 0 ? i : (i ^ 0x7FFFFFFF);
}
__device__ __forceinline__ float dec_f(int i) {
    int j = i >= 0 ? i : (i ^ 0x7FFFFFFF);
    return __int_as_float(j);
}

__device__ __forceinline__ void red_add_v4(float* p, float4 v) {
    asm volatile("red.global.add.v4.f32 [%0], {%1,%2,%3,%4};"
                 :: "l"(p), "f"(v.x), "f"(v.y), "f"(v.z), "f"(v.w) : "memory");
}

// ---------------- init scratch ----------------
__global__ void k_init(int N, int G) {
    int i = blockIdx.x * blockDim.x + threadIdx.x;
    int total = N * HDIM;
    if (i < total) g_agg[i] = 0.f;
    if (i < N) g_deg[i] = 0;
    if (i < G * HDIM) { g_pool_add[i] = 0.f; g_pool_max[i] = (int)0x80000000; }
    if (i < G) g_count[i] = 0;
}

// ---------------- degree histogram ----------------
__global__ void k_deg(const int* __restrict__ ei, int E) {
    int e = blockIdx.x * blockDim.x + threadIdx.x;
    if (e < E) atomicAdd(&g_deg[ei[E + e]], 1);
}

__global__ void k_dinv(int N) {
    int i = blockIdx.x * blockDim.x + threadIdx.x;
    if (i < N) g_dinv[i] = rsqrtf((float)g_deg[i] + 1.0f);
}

// ---------------- h = x @ W  (register-tiled SGEMM, BM=64, BN=128, BK=16) ----------------
__global__ __launch_bounds__(256) void k_gemm(const float* __restrict__ X,
                                              const float* __restrict__ W, int N) {
    __shared__ float As[16][68];    // [k][m], padded
    __shared__ float Bs[16][128];   // [k][n]
    int tid = threadIdx.x;
    int row0 = blockIdx.x * 64;
    int tx = tid & 15;   // n-group: cols tx*8 .. +7
    int ty = tid >> 4;   // m-group: rows ty*4 .. +3

    float acc[4][8];
#pragma unroll
    for (int i = 0; i < 4; i++)
#pragma unroll
        for (int j = 0; j < 8; j++) acc[i][j] = 0.f;

    int lr = tid >> 2;          // A-load row in tile (0..63)
    int lk = (tid & 3) * 4;     // A-load k offset (0,4,8,12)
    int wr = tid >> 4;          // B-load k row (0..15)
    int wc = (tid & 15) * 8;    // B-load col

    for (int k0 = 0; k0 < 128; k0 += 16) {
        int grow = row0 + lr;
        float4 av = (grow < N) ? *(const float4*)(X + (size_t)grow * 128 + k0 + lk)
                               : make_float4(0.f, 0.f, 0.f, 0.f);
        As[lk + 0][lr] = av.x; As[lk + 1][lr] = av.y;
        As[lk + 2][lr] = av.z; As[lk + 3][lr] = av.w;

        float4 b0 = *(const float4*)(W + (size_t)(k0 + wr) * 128 + wc);
        float4 b1 = *(const float4*)(W + (size_t)(k0 + wr) * 128 + wc + 4);
        *(float4*)&Bs[wr][wc] = b0;
        *(float4*)&Bs[wr][wc + 4] = b1;
        __syncthreads();

#pragma unroll
        for (int k = 0; k < 16; k++) {
            float4 a  = *(const float4*)&As[k][ty * 4];
            float4 bA = *(const float4*)&Bs[k][tx * 8];
            float4 bB = *(const float4*)&Bs[k][tx * 8 + 4];
            float am[4] = {a.x, a.y, a.z, a.w};
            float bn[8] = {bA.x, bA.y, bA.z, bA.w, bB.x, bB.y, bB.z, bB.w};
#pragma unroll
            for (int i = 0; i < 4; i++)
#pragma unroll
                for (int j = 0; j < 8; j++) acc[i][j] = fmaf(am[i], bn[j], acc[i][j]);
        }
        __syncthreads();
    }

#pragma unroll
    for (int i = 0; i < 4; i++) {
        int r = row0 + ty * 4 + i;
        if (r < N) {
            float4 o0 = make_float4(acc[i][0], acc[i][1], acc[i][2], acc[i][3]);
            float4 o1 = make_float4(acc[i][4], acc[i][5], acc[i][6], acc[i][7]);
            *(float4*)(g_h + (size_t)r * 128 + tx * 8) = o0;
            *(float4*)(g_h + (size_t)r * 128 + tx * 8 + 4) = o1;
        }
    }
}

// ---------------- edge scatter: agg[dst] += h[src] * dinv[src]*dinv[dst] ----------------
__global__ __launch_bounds__(256) void k_edge(const int* __restrict__ ei, int E) {
    int t = blockIdx.x * blockDim.x + threadIdx.x;
    int e = t >> 5;
    int lane = t & 31;
    if (e >= E) return;
    int src = ei[e];
    int dst = ei[E + e];
    float coef = g_dinv[src] * g_dinv[dst];
    float4 v = *(const float4*)(g_h + (size_t)src * 128 + lane * 4);
    v.x *= coef; v.y *= coef; v.z *= coef; v.w *= coef;
    red_add_v4(g_agg + (size_t)dst * 128 + lane * 4, v);
}

// ---------------- node epilogue: self-loop + bias + ReLU + LayerNorm + pooled reduce ----------------
__global__ __launch_bounds__(256) void k_node(const int* __restrict__ batch,
                                              const float* __restrict__ bgcn,
                                              const float* __restrict__ gamma,
                                              const float* __restrict__ beta,
                                              int N) {
    __shared__ float s_sum[128];
    __shared__ int   s_max[128];
    __shared__ int   s_cnt;
    int node0 = blockIdx.x * 8;
    if (node0 >= N) return;
    int tid = threadIdx.x;
    int warp = tid >> 5, lane = tid & 31;

    int lastnode = min(node0 + 7, N - 1);
    int gid0 = batch[node0];
    int gid1 = batch[lastnode];
    bool uniform = (gid0 == gid1);

    if (tid < 128) { s_sum[tid] = 0.f; s_max[tid] = (int)0x80000000; }
    if (tid == 0) s_cnt = 0;
    __syncthreads();

    int node = node0 + warp;
    if (node < N) {
        float di = g_dinv[node];
        float sl = di * di;
        float4 a  = *(const float4*)(g_agg + (size_t)node * 128 + lane * 4);
        float4 hh = *(const float4*)(g_h   + (size_t)node * 128 + lane * 4);
        float4 b4 = *(const float4*)(bgcn + lane * 4);
        float v0 = fmaxf(fmaf(hh.x, sl, a.x) + b4.x, 0.f);
        float v1 = fmaxf(fmaf(hh.y, sl, a.y) + b4.y, 0.f);
        float v2 = fmaxf(fmaf(hh.z, sl, a.z) + b4.z, 0.f);
        float v3 = fmaxf(fmaf(hh.w, sl, a.w) + b4.w, 0.f);

        float s  = v0 + v1 + v2 + v3;
        float sq = v0 * v0 + v1 * v1 + v2 * v2 + v3 * v3;
#pragma unroll
        for (int o = 16; o; o >>= 1) {
            s  += __shfl_xor_sync(0xFFFFFFFFu, s, o);
            sq += __shfl_xor_sync(0xFFFFFFFFu, sq, o);
        }
        float mean = s * (1.f / 128.f);
        float var  = sq * (1.f / 128.f) - mean * mean;
        float inv  = rsqrtf(var + 1e-5f);
        float4 gm = *(const float4*)(gamma + lane * 4);
        float4 bt = *(const float4*)(beta + lane * 4);
        float y0 = fmaf((v0 - mean) * inv, gm.x, bt.x);
        float y1 = fmaf((v1 - mean) * inv, gm.y, bt.y);
        float y2 = fmaf((v2 - mean) * inv, gm.z, bt.z);
        float y3 = fmaf((v3 - mean) * inv, gm.w, bt.w);

        if (uniform) {
            atomicAdd(&s_sum[lane * 4 + 0], y0);
            atomicAdd(&s_sum[lane * 4 + 1], y1);
            atomicAdd(&s_sum[lane * 4 + 2], y2);
            atomicAdd(&s_sum[lane * 4 + 3], y3);
            atomicMax(&s_max[lane * 4 + 0], enc_f(y0));
            atomicMax(&s_max[lane * 4 + 1], enc_f(y1));
            atomicMax(&s_max[lane * 4 + 2], enc_f(y2));
            atomicMax(&s_max[lane * 4 + 3], enc_f(y3));
            if (lane == 0) atomicAdd(&s_cnt, 1);
        } else {
            int gid = batch[node];
            float* pa = g_pool_add + (size_t)gid * 128 + lane * 4;
            atomicAdd(pa + 0, y0); atomicAdd(pa + 1, y1);
            atomicAdd(pa + 2, y2); atomicAdd(pa + 3, y3);
            int* pm = g_pool_max + (size_t)gid * 128 + lane * 4;
            atomicMax(pm + 0, enc_f(y0)); atomicMax(pm + 1, enc_f(y1));
            atomicMax(pm + 2, enc_f(y2)); atomicMax(pm + 3, enc_f(y3));
            if (lane == 0) atomicAdd(&g_count[gid], 1);
        }
    }
    __syncthreads();
    if (uniform && tid < 128) {
        atomicAdd(&g_pool_add[(size_t)gid0 * 128 + tid], s_sum[tid]);
        atomicMax(&g_pool_max[(size_t)gid0 * 128 + tid], s_max[tid]);
    }
    if (uniform && tid == 0 && s_cnt > 0) atomicAdd(&g_count[gid0], s_cnt);
}

// ---------------- MLP head: one block per graph ----------------
__global__ __launch_bounds__(128) void k_mlp(const float* __restrict__ W1, const float* __restrict__ b1,
                                             const float* __restrict__ W2, const float* __restrict__ b2,
                                             const float* __restrict__ W3, const float* __restrict__ b3,
                                             float* __restrict__ out, int G) {
    __shared__ float sg[384];
    __shared__ float s1[128];
    __shared__ float s2[64];
    int gid = blockIdx.x;
    int tid = threadIdx.x;
    int cnt = g_count[gid];
    float c = fmaxf((float)cnt, 1.f);
    if (tid < 128) {
        float add = g_pool_add[(size_t)gid * 128 + tid];
        float mx  = (cnt > 0) ? dec_f(g_pool_max[(size_t)gid * 128 + tid]) : 0.f;
        sg[tid]       = add / c;   // mean
        sg[128 + tid] = add;       // add
        sg[256 + tid] = mx;        // max
    }
    __syncthreads();

    float acc = b1[tid];
#pragma unroll 8
    for (int k = 0; k < 384; k++) acc = fmaf(sg[k], W1[(size_t)k * 128 + tid], acc);
    s1[tid] = fmaxf(acc, 0.f);
    __syncthreads();

    if (tid < 64) {
        float a = b2[tid];
#pragma unroll 8
        for (int k = 0; k < 128; k++) a = fmaf(s1[k], W2[(size_t)k * 64 + tid], a);
        s2[tid] = fmaxf(a, 0.f);
    }
    __syncthreads();

    if (tid < 10) {
        float a = b3[tid];
#pragma unroll
        for (int k = 0; k < 64; k++) a = fmaf(s2[k], W3[(size_t)k * 10 + tid], a);
        out[gid * 10 + tid] = a;
    }
}

extern "C" void kernel_launch(void* const* d_in, const int* in_sizes, int n_in,
                              void* d_out, int out_size) {
    const float* x     = (const float*)d_in[0];
    const int*   ei    = (const int*)d_in[1];
    const int*   batch = (const int*)d_in[2];
    // d_in[3] = num_graphs (unused; G from out_size)
    const float* Wg    = (const float*)d_in[4];
    const float* bg    = (const float*)d_in[5];
    const float* gamma = (const float*)d_in[6];
    const float* beta  = (const float*)d_in[7];
    const float* W1    = (const float*)d_in[8];
    const float* b1    = (const float*)d_in[9];
    const float* W2    = (const float*)d_in[10];
    const float* b2    = (const float*)d_in[11];
    const float* W3    = (const float*)d_in[12];
    const float* b3    = (const float*)d_in[13];
    float* out = (float*)d_out;

    int N = in_sizes[0] / HDIM;
    int E = in_sizes[1] / 2;
    int G = out_size / 10;

    int total = N * HDIM;
    k_init<<<(total + 255) / 256, 256>>>(N, G);
    k_deg<<<(E + 255) / 256, 256>>>(ei, E);
    k_dinv<<<(N + 255) / 256, 256>>>(N);
    k_gemm<<<(N + 63) / 64, 256>>>(x, Wg, N);
    long long ethreads = (long long)E * 32;
    k_edge<<<(int)((ethreads + 255) / 256), 256>>>(ei, E);
    k_node<<<(N + 7) / 8, 256>>>(batch, bg, gamma, beta, N);
    k_mlp<<<G, 128>>>(W1, b1, W2, b2, W3, b3, out, G);
}